// round 8
// baseline (speedup 1.0000x reference)
#include <cuda_runtime.h>
#include <cuda_bf16.h>

#define N_ATOM 30000
#define N_PAIR 1000000
#define N_TRI  4000000
#define N_SF   16
#define RC2    36.0f
#define U_SCALE 0.27415567780803773f  // pi^2 / 36

// 16B per pair: {dx, dy, dz, rind-as-float-bits}. fc recomputed from d^2.
__device__ float4        g_pair[N_PAIR];      // 16MB scratch
__device__ int           g_pair_max[N_PAIR];  // ik-side segment max
__device__ unsigned char g_flag[N_PAIR];      // ij-side participation flag

__global__ void dummy_kernel() {}

// ---------------------------------------------------------------------------
// K: pack pair data + init flags/max + zero fp — 2 pairs/thread, loads hoisted
// ---------------------------------------------------------------------------
__global__ void __launch_bounds__(256) pack_init_kernel(
    const int*   __restrict__ ind2,
    const float* __restrict__ diff,
    float* __restrict__ fp)
{
    int v = blockIdx.x * blockDim.x + threadIdx.x;
    int p0 = 2 * v;
    int p1 = 2 * v + 1;
    if (p1 < N_PAIR) {
        // hoist all loads: MLP
        float d0x = __ldg(diff + 3 * p0);
        float d0y = __ldg(diff + 3 * p0 + 1);
        float d0z = __ldg(diff + 3 * p0 + 2);
        float d1x = __ldg(diff + 3 * p1);
        float d1y = __ldg(diff + 3 * p1 + 1);
        float d1z = __ldg(diff + 3 * p1 + 2);
        int4 ri2 = __ldg(reinterpret_cast<const int4*>(ind2 + 4 * v)); // p0:(x,y) p1:(z,w)
        g_pair[p0] = make_float4(d0x, d0y, d0z, __int_as_float(ri2.x));
        g_pair[p1] = make_float4(d1x, d1y, d1z, __int_as_float(ri2.z));
        g_pair_max[p0] = -1;
        g_pair_max[p1] = -1;
        g_flag[p0] = 0;
        g_flag[p1] = 0;
    }
    if (v < N_ATOM * N_SF) fp[v] = 0.0f;
}

// Vector reduction: 4 floats, one REDG (sm_90+)
__device__ __forceinline__ void red_add_v4(float* addr, float a, float b, float c, float d)
{
    asm volatile("red.global.add.v4.f32 [%0], {%1, %2, %3, %4};"
                 :: "l"(addr), "f"(a), "f"(b), "f"(c), "f"(d) : "memory");
}

// 0.5*(cos(pi*sqrt(x)/6)+1) as poly in u = (pi^2/36)*x; |err| < ~4e-9 on [0, pi^2].
__device__ __forceinline__ float fc_from_d2(float d2)
{
    float u = d2 * U_SCALE;
    float p = -2.7557319e-07f;
    p = fmaf(p, u,  2.4801587e-05f);
    p = fmaf(p, u, -1.3888889e-03f);
    p = fmaf(p, u,  4.1666667e-02f);
    p = fmaf(p, u, -0.5f);
    p = fmaf(p, u,  1.0f);
    float u2 = u * u;
    float u3 = u2 * u;
    float corr = u3 * u3 * (2.0876757e-09f
               + u * (-1.1470746e-11f
               + u * ( 4.7794773e-14f
               + u * (-1.5619207e-16f))));
    return 0.5f * ((p + corr) + 1.0f);
}

// Process one triple given its preloaded pair packets.
__device__ __forceinline__ void do_triple(int ij, int ik, float4 A, float4 B,
                                          float* __restrict__ fp)
{
    float jx = B.x - A.x, jy = B.y - A.y, jz = B.z - A.z;
    float djk2 = jx * jx + jy * jy + jz * jz;
    if (djk2 >= RC2) return;

    int i_rind = __float_as_int(A.w);

    // issue the cheap per-pair state ops early; they overlap the math below
    g_flag[ij] = 1;
    atomicMax(&g_pair_max[ik], i_rind);

    float dij2 = A.x * A.x + A.y * A.y + A.z * A.z;
    float dik2 = B.x * B.x + B.y * B.y + B.z * B.z;

    float fcij = fc_from_d2(dij2);
    float fcik = fc_from_d2(dik2);
    float fcjk = fc_from_d2(djk2);

    float dot  = A.x * B.x + A.y * B.y + A.z * B.z;
    float cosv = dot * rsqrtf(dij2 * dik2);

    float a = fmaxf(1.0f - cosv, 0.0f);
    float b = fmaxf(1.0f + cosv, 0.0f);

    float P  = fcij * fcik * fcjk;
    float Ph = 0.5f * P, Pq = 0.125f * P, Pe = 0.0078125f * P;

    float a2 = a * a,  b2 = b * b;
    float a4 = a2 * a2, b4 = b2 * b2;
    float a8 = a4 * a4, b8 = b4 * b4;

    float q0 = a  * P,  q1 = b  * P;
    float q2 = a2 * Ph, q3 = b2 * Ph;
    float q4 = a4 * Pq, q5 = b4 * Pq;
    float q6 = a8 * Pe, q7 = b8 * Pe;

    float s = dij2 + dik2 + djk2;

    float e1  = __expf(-0.01f  * s);
    float e14 = __expf(-0.014f * s);

    float e2   = e1  * e1;
    float e4   = e2  * e2;
    float e8   = e4  * e4;
    float e16  = e8  * e8;
    float e32  = e16 * e16;
    float e64  = e32 * e32;
    float e3   = e2  * e1;
    float e11  = e8  * e3;
    float e22  = e11 * e11;
    float e44  = e22 * e22;
    float e45  = e44 * e1;
    float e63  = e45 * (e16 * e2);
    float e72  = e64 * e8;
    float e90  = e45 * e45;
    float e100 = e64 * (e32 * e4);
    float e14_2 = e14 * e14;
    float e14_4 = e14_2 * e14_2;

    float* dst = fp + i_rind * N_SF;
    red_add_v4(dst +  0, q0 * e1,   q1 * e14,   q2 * e2,   q3 * e14_2);
    red_add_v4(dst +  4, q4 * e4,   q5 * e14_4, q6 * e8,   q7 * e11);
    red_add_v4(dst +  8, q0 * e16,  q1 * e22,   q2 * e32,  q3 * e45);
    red_add_v4(dst + 12, q4 * e63,  q5 * e72,   q6 * e90,  q7 * e100);
}

// ---------------------------------------------------------------------------
// K: main triple loop — 4 triples/thread, 128-thread blocks (occ 50% @57regs)
// ---------------------------------------------------------------------------
__global__ void __launch_bounds__(128) tri_kernel(
    const int4* __restrict__ ind3v,   // [N_TRI/2]
    float* __restrict__ fp)
{
    int v = blockIdx.x * blockDim.x + threadIdx.x;
    if (v >= N_TRI / 4) return;

    int4 qa = __ldg(&ind3v[2 * v]);
    int4 qb = __ldg(&ind3v[2 * v + 1]);

    // Batch all eight gathers: MLP=8 before any dependent math.
    float4 A1 = __ldg(&g_pair[qa.x]);
    float4 B1 = __ldg(&g_pair[qa.y]);
    float4 A2 = __ldg(&g_pair[qa.z]);
    float4 B2 = __ldg(&g_pair[qa.w]);
    float4 A3 = __ldg(&g_pair[qb.x]);
    float4 B3 = __ldg(&g_pair[qb.y]);
    float4 A4 = __ldg(&g_pair[qb.z]);
    float4 B4 = __ldg(&g_pair[qb.w]);

    do_triple(qa.x, qa.y, A1, B1, fp);
    do_triple(qa.z, qa.w, A2, B2, fp);
    do_triple(qb.x, qb.y, A3, B3, fp);
    do_triple(qb.z, qb.w, A4, B4, fp);
}

// ---------------------------------------------------------------------------
// K: jacob_ind = [arange, max(flag ? rind : -1, ik_max)]
// ---------------------------------------------------------------------------
__global__ void __launch_bounds__(256) jac_kernel(float2* __restrict__ out_j)
{
    int p = blockIdx.x * blockDim.x + threadIdx.x;
    if (p < N_PAIR) {
        int ikmax = g_pair_max[p];
        int rv    = g_flag[p] ? __float_as_int(g_pair[p].w) : -1;
        int v     = ikmax > rv ? ikmax : rv;
        out_j[p] = make_float2((float)p, (float)v);
    }
}

// ---------------------------------------------------------------------------
// Launch. Inputs: ind_2, ind_3, dist(unused), diff, elems(unused), fc(unused)
// ---------------------------------------------------------------------------
extern "C" void kernel_launch(void* const* d_in, const int* in_sizes, int n_in,
                              void* d_out, int out_size)
{
    const int*  ind2  = (const int*)d_in[0];
    const int4* ind3v = (const int4*)d_in[1];
    const float* diff = (const float*)d_in[3];

    float*  fp    = (float*)d_out;
    float2* out_j = (float2*)((float*)d_out + N_ATOM * N_SF);

    dummy_kernel<<<1, 32>>>();   // idx 0
    dummy_kernel<<<1, 32>>>();   // idx 1
    // pack covers max(N_PAIR/2, N_ATOM*N_SF) work items
    int pack_items = (N_PAIR / 2) > (N_ATOM * N_SF) ? (N_PAIR / 2) : (N_ATOM * N_SF);
    pack_init_kernel<<<(pack_items + 255) / 256, 256>>>(ind2, diff, fp);  // idx 2
    tri_kernel<<<(N_TRI / 4 + 127) / 128, 128>>>(ind3v, fp);              // idx 3 (profiled)
    jac_kernel<<<(N_PAIR + 255) / 256, 256>>>(out_j);                     // idx 4
}

// round 10
// speedup vs baseline: 1.1186x; 1.1186x over previous
#include <cuda_runtime.h>
#include <cuda_fp16.h>
#include <cuda_bf16.h>

#define N_ATOM 30000
#define N_PAIR 1000000
#define N_TRI  4000000
#define N_SF   16
#define RC2    36.0f
#define U_SCALE 0.27415567780803773f  // pi^2 / 36

// 16B per pair: {dx, dy, dz, rind-as-float-bits}.
__device__ float4        g_pair[N_PAIR];      // 16MB scratch
__device__ int           g_rind[N_PAIR];      // compact rind copy (coalesced jac reads)
__device__ int           g_pair_max[N_PAIR];  // ik-side segment max
__device__ unsigned char g_flag[N_PAIR];      // ij-side participation flag
// fp16 accumulators for channels 8-15: 8 halves = 16B per atom row.
__device__ __align__(16) unsigned g_fp_hi[N_ATOM * 4];

__global__ void dummy_kernel() {}

// ---------------------------------------------------------------------------
// K: pack pair data + init everything (1 pair/thread — R6-proven form)
// ---------------------------------------------------------------------------
__global__ void __launch_bounds__(256) pack_init_kernel(
    const int*   __restrict__ ind2,
    const float* __restrict__ diff,
    float* __restrict__ fp)
{
    int p = blockIdx.x * blockDim.x + threadIdx.x;
    if (p < N_PAIR) {
        float dx = __ldg(diff + 3 * p);
        float dy = __ldg(diff + 3 * p + 1);
        float dz = __ldg(diff + 3 * p + 2);
        int   ri = __ldg(ind2 + 2 * p);
        g_pair[p] = make_float4(dx, dy, dz, __int_as_float(ri));
        g_rind[p] = ri;
        g_pair_max[p] = -1;
        g_flag[p] = 0;
    }
    if (p < N_ATOM * N_SF) fp[p] = 0.0f;
    if (p < N_ATOM * 4)    g_fp_hi[p] = 0u;
}

// 128-bit f32 vector reduction (channels 0-7 in two halves? no: 0-3 / 4-7)
__device__ __forceinline__ void red_add_v4(float* addr, float a, float b, float c, float d)
{
    asm volatile("red.global.add.v4.f32 [%0], {%1, %2, %3, %4};"
                 :: "l"(addr), "f"(a), "f"(b), "f"(c), "f"(d) : "memory");
}

// 128-bit packed-half vector reduction: 8 fp16 channels in ONE RED.
__device__ __forceinline__ void red_add_h8(unsigned* addr,
                                           unsigned h0, unsigned h1,
                                           unsigned h2, unsigned h3)
{
    asm volatile("red.global.add.noftz.v4.f16x2 [%0], {%1, %2, %3, %4};"
                 :: "l"(addr), "r"(h0), "r"(h1), "r"(h2), "r"(h3) : "memory");
}

__device__ __forceinline__ unsigned pack_h2(float x, float y)
{
    __half2 h = __floats2half2_rn(x, y);
    return *reinterpret_cast<unsigned*>(&h);
}

// 0.5*(cos(pi*sqrt(x)/6)+1) as poly in u = (pi^2/36)*x; |err| < ~4e-9 on [0, pi^2].
__device__ __forceinline__ float fc_from_d2(float d2)
{
    float u = d2 * U_SCALE;
    float p = -2.7557319e-07f;
    p = fmaf(p, u,  2.4801587e-05f);
    p = fmaf(p, u, -1.3888889e-03f);
    p = fmaf(p, u,  4.1666667e-02f);
    p = fmaf(p, u, -0.5f);
    p = fmaf(p, u,  1.0f);
    float u2 = u * u;
    float u3 = u2 * u;
    float corr = u3 * u3 * (2.0876757e-09f
               + u * (-1.1470746e-11f
               + u * ( 4.7794773e-14f
               + u * (-1.5619207e-16f))));
    return 0.5f * ((p + corr) + 1.0f);
}

// Process one triple given its preloaded pair packets.
__device__ __forceinline__ void do_triple(int ij, int ik, float4 A, float4 B,
                                          float* __restrict__ fp)
{
    float jx = B.x - A.x, jy = B.y - A.y, jz = B.z - A.z;
    float djk2 = jx * jx + jy * jy + jz * jz;
    if (djk2 >= RC2) return;

    int i_rind = __float_as_int(A.w);

    g_flag[ij] = 1;                        // ij-side: idempotent flag
    atomicMax(&g_pair_max[ik], i_rind);    // ik-side: true max

    float dij2 = A.x * A.x + A.y * A.y + A.z * A.z;
    float dik2 = B.x * B.x + B.y * B.y + B.z * B.z;

    float fcij = fc_from_d2(dij2);
    float fcik = fc_from_d2(dik2);
    float fcjk = fc_from_d2(djk2);

    float dot  = A.x * B.x + A.y * B.y + A.z * B.z;
    float cosv = dot * rsqrtf(dij2 * dik2);

    float a = fmaxf(1.0f - cosv, 0.0f);
    float b = fmaxf(1.0f + cosv, 0.0f);

    float P  = fcij * fcik * fcjk;
    float Ph = 0.5f * P, Pq = 0.125f * P, Pe = 0.0078125f * P;

    float a2 = a * a,  b2 = b * b;
    float a4 = a2 * a2, b4 = b2 * b2;
    float a8 = a4 * a4, b8 = b4 * b4;

    float q0 = a  * P,  q1 = b  * P;
    float q2 = a2 * Ph, q3 = b2 * Ph;
    float q4 = a4 * Pq, q5 = b4 * Pq;
    float q6 = a8 * Pe, q7 = b8 * Pe;

    float s = dij2 + dik2 + djk2;

    float e1  = __expf(-0.01f  * s);
    float e14 = __expf(-0.014f * s);

    float e2   = e1  * e1;
    float e4   = e2  * e2;
    float e8   = e4  * e4;
    float e16  = e8  * e8;
    float e32  = e16 * e16;
    float e64  = e32 * e32;
    float e3   = e2  * e1;
    float e11  = e8  * e3;
    float e22  = e11 * e11;
    float e44  = e22 * e22;
    float e45  = e44 * e1;
    float e63  = e45 * (e16 * e2);
    float e72  = e64 * e8;
    float e90  = e45 * e45;
    float e100 = e64 * (e32 * e4);
    float e14_2 = e14 * e14;
    float e14_4 = e14_2 * e14_2;

    // channels 0-7: fp32, two 128-bit REDs
    float* dst = fp + i_rind * N_SF;
    red_add_v4(dst,     q0 * e1, q1 * e14,   q2 * e2, q3 * e14_2);
    red_add_v4(dst + 4, q4 * e4, q5 * e14_4, q6 * e8, q7 * e11);

    // channels 8-15: fp16 packed, ONE 128-bit RED
    unsigned h0 = pack_h2(q0 * e16, q1 * e22);
    unsigned h1 = pack_h2(q2 * e32, q3 * e45);
    unsigned h2 = pack_h2(q4 * e63, q5 * e72);
    unsigned h3 = pack_h2(q6 * e90, q7 * e100);
    red_add_h8(g_fp_hi + 4 * i_rind, h0, h1, h2, h3);
}

// ---------------------------------------------------------------------------
// K: main triple loop — 2 triples/thread (R6-best shape), gathers batched.
// ---------------------------------------------------------------------------
__global__ void __launch_bounds__(256) tri_kernel(
    const int4* __restrict__ ind3v,   // [N_TRI/2]
    float* __restrict__ fp)
{
    int v = blockIdx.x * blockDim.x + threadIdx.x;
    if (v >= N_TRI / 2) return;
    int4 q = __ldg(&ind3v[v]);

    float4 A1 = __ldg(&g_pair[q.x]);
    float4 B1 = __ldg(&g_pair[q.y]);
    float4 A2 = __ldg(&g_pair[q.z]);
    float4 B2 = __ldg(&g_pair[q.w]);

    do_triple(q.x, q.y, A1, B1, fp);
    do_triple(q.z, q.w, A2, B2, fp);
}

// ---------------------------------------------------------------------------
// K: jacob_ind + convert fp16 channel accumulators to fp32 output
// ---------------------------------------------------------------------------
__global__ void __launch_bounds__(256) jac_kernel(float2* __restrict__ out_j,
                                                 float* __restrict__ fp)
{
    int p = blockIdx.x * blockDim.x + threadIdx.x;
    if (p < N_PAIR) {
        int ikmax = g_pair_max[p];
        int rv    = g_flag[p] ? g_rind[p] : -1;
        int v     = ikmax > rv ? ikmax : rv;
        out_j[p] = make_float2((float)p, (float)v);
    }
    if (p < N_ATOM) {
        uint4 raw = *reinterpret_cast<const uint4*>(g_fp_hi + 4 * p);
        float2 f0 = __half22float2(*reinterpret_cast<__half2*>(&raw.x));
        float2 f1 = __half22float2(*reinterpret_cast<__half2*>(&raw.y));
        float2 f2 = __half22float2(*reinterpret_cast<__half2*>(&raw.z));
        float2 f3 = __half22float2(*reinterpret_cast<__half2*>(&raw.w));
        float4* dst = reinterpret_cast<float4*>(fp + p * N_SF + 8);
        dst[0] = make_float4(f0.x, f0.y, f1.x, f1.y);
        dst[1] = make_float4(f2.x, f2.y, f3.x, f3.y);
    }
}

// ---------------------------------------------------------------------------
// Launch. Inputs: ind_2, ind_3, dist(unused), diff, elems(unused), fc(unused)
// ---------------------------------------------------------------------------
extern "C" void kernel_launch(void* const* d_in, const int* in_sizes, int n_in,
                              void* d_out, int out_size)
{
    const int*  ind2  = (const int*)d_in[0];
    const int4* ind3v = (const int4*)d_in[1];
    const float* diff = (const float*)d_in[3];

    float*  fp    = (float*)d_out;
    float2* out_j = (float2*)((float*)d_out + N_ATOM * N_SF);

    dummy_kernel<<<1, 32>>>();   // idx 0
    dummy_kernel<<<1, 32>>>();   // idx 1
    pack_init_kernel<<<(N_PAIR + 255) / 256, 256>>>(ind2, diff, fp);  // idx 2
    tri_kernel<<<(N_TRI / 2 + 255) / 256, 256>>>(ind3v, fp);          // idx 3 (profiled)
    jac_kernel<<<(N_PAIR + 255) / 256, 256>>>(out_j, fp);             // idx 4
}

// round 11
// speedup vs baseline: 1.1498x; 1.0279x over previous
#include <cuda_runtime.h>
#include <cuda_fp16.h>
#include <cuda_bf16.h>

#define N_ATOM 30000
#define N_PAIR 1000000
#define N_TRI  4000000
#define N_SF   16
#define RC2    36.0f
#define U_SCALE 0.27415567780803773f  // pi^2 / 36

// 16B per pair: {dx, dy, dz, rind-as-float-bits}.
__device__ float4        g_pair[N_PAIR];      // 16MB scratch
__device__ int           g_rind[N_PAIR];      // compact rind copy (coalesced jac reads)
__device__ int           g_pair_max[N_PAIR];  // ik-side segment max
__device__ unsigned char g_flag[N_PAIR];      // ij-side participation flag
// fp16 accumulators for channels 8-15: 8 halves = 16B per atom row.
__device__ __align__(16) unsigned g_fp_hi[N_ATOM * 4];

// ---------------------------------------------------------------------------
// K: pack pair data + init everything
// ---------------------------------------------------------------------------
__global__ void __launch_bounds__(256) pack_init_kernel(
    const int*   __restrict__ ind2,
    const float* __restrict__ diff,
    float* __restrict__ fp)
{
    int p = blockIdx.x * blockDim.x + threadIdx.x;
    if (p < N_PAIR) {
        float dx = __ldg(diff + 3 * p);
        float dy = __ldg(diff + 3 * p + 1);
        float dz = __ldg(diff + 3 * p + 2);
        int   ri = __ldg(ind2 + 2 * p);
        g_pair[p] = make_float4(dx, dy, dz, __int_as_float(ri));
        g_rind[p] = ri;
        g_pair_max[p] = -1;
        g_flag[p] = 0;
    }
    if (p < N_ATOM * N_SF) fp[p] = 0.0f;
    if (p < N_ATOM * 4)    g_fp_hi[p] = 0u;
}

// 128-bit f32 vector reduction
__device__ __forceinline__ void red_add_v4(float* addr, float a, float b, float c, float d)
{
    asm volatile("red.global.add.v4.f32 [%0], {%1, %2, %3, %4};"
                 :: "l"(addr), "f"(a), "f"(b), "f"(c), "f"(d) : "memory");
}

// 128-bit packed-half vector reduction: 8 fp16 channels in ONE RED.
__device__ __forceinline__ void red_add_h8(unsigned* addr,
                                           unsigned h0, unsigned h1,
                                           unsigned h2, unsigned h3)
{
    asm volatile("red.global.add.noftz.v4.f16x2 [%0], {%1, %2, %3, %4};"
                 :: "l"(addr), "r"(h0), "r"(h1), "r"(h2), "r"(h3) : "memory");
}

__device__ __forceinline__ unsigned pack_h2(float x, float y)
{
    __half2 h = __floats2half2_rn(x, y);
    return *reinterpret_cast<unsigned*>(&h);
}

// 0.5*(cos(pi*sqrt(x)/6)+1) as poly in u = (pi^2/36)*x; |err| < ~4e-9 on [0, pi^2].
__device__ __forceinline__ float fc_from_d2(float d2)
{
    float u = d2 * U_SCALE;
    float p = -2.7557319e-07f;
    p = fmaf(p, u,  2.4801587e-05f);
    p = fmaf(p, u, -1.3888889e-03f);
    p = fmaf(p, u,  4.1666667e-02f);
    p = fmaf(p, u, -0.5f);
    p = fmaf(p, u,  1.0f);
    float u2 = u * u;
    float u3 = u2 * u;
    float corr = u3 * u3 * (2.0876757e-09f
               + u * (-1.1470746e-11f
               + u * ( 4.7794773e-14f
               + u * (-1.5619207e-16f))));
    return 0.5f * ((p + corr) + 1.0f);
}

// Process one triple given its preloaded pair packets.
__device__ __forceinline__ void do_triple(int ij, int ik, float4 A, float4 B,
                                          float* __restrict__ fp)
{
    float jx = B.x - A.x, jy = B.y - A.y, jz = B.z - A.z;
    float djk2 = jx * jx + jy * jy + jz * jz;
    if (djk2 >= RC2) return;

    int i_rind = __float_as_int(A.w);

    g_flag[ij] = 1;                        // ij-side: idempotent flag
    atomicMax(&g_pair_max[ik], i_rind);    // ik-side: true max

    float dij2 = A.x * A.x + A.y * A.y + A.z * A.z;
    float dik2 = B.x * B.x + B.y * B.y + B.z * B.z;

    float fcij = fc_from_d2(dij2);
    float fcik = fc_from_d2(dik2);
    float fcjk = fc_from_d2(djk2);

    float dot  = A.x * B.x + A.y * B.y + A.z * B.z;
    float cosv = dot * rsqrtf(dij2 * dik2);

    float a = fmaxf(1.0f - cosv, 0.0f);
    float b = fmaxf(1.0f + cosv, 0.0f);

    float P  = fcij * fcik * fcjk;
    float Ph = 0.5f * P, Pq = 0.125f * P, Pe = 0.0078125f * P;

    float a2 = a * a,  b2 = b * b;
    float a4 = a2 * a2, b4 = b2 * b2;
    float a8 = a4 * a4, b8 = b4 * b4;

    float q0 = a  * P,  q1 = b  * P;
    float q2 = a2 * Ph, q3 = b2 * Ph;
    float q4 = a4 * Pq, q5 = b4 * Pq;
    float q6 = a8 * Pe, q7 = b8 * Pe;

    float s = dij2 + dik2 + djk2;

    float e1  = __expf(-0.01f  * s);
    float e14 = __expf(-0.014f * s);

    float e2   = e1  * e1;
    float e4   = e2  * e2;
    float e8   = e4  * e4;
    float e16  = e8  * e8;
    float e32  = e16 * e16;
    float e64  = e32 * e32;
    float e3   = e2  * e1;
    float e11  = e8  * e3;
    float e22  = e11 * e11;
    float e44  = e22 * e22;
    float e45  = e44 * e1;
    float e63  = e45 * (e16 * e2);
    float e72  = e64 * e8;
    float e90  = e45 * e45;
    float e100 = e64 * (e32 * e4);
    float e14_2 = e14 * e14;
    float e14_4 = e14_2 * e14_2;

    // channels 0-7: fp32, two 128-bit REDs
    float* dst = fp + i_rind * N_SF;
    red_add_v4(dst,     q0 * e1, q1 * e14,   q2 * e2, q3 * e14_2);
    red_add_v4(dst + 4, q4 * e4, q5 * e14_4, q6 * e8, q7 * e11);

    // channels 8-15: fp16 packed, ONE 128-bit RED.
    // Skip entirely when every half rounds to +0 (adding 0 is exact identity).
    unsigned h0 = pack_h2(q0 * e16, q1 * e22);
    unsigned h1 = pack_h2(q2 * e32, q3 * e45);
    unsigned h2 = pack_h2(q4 * e63, q5 * e72);
    unsigned h3 = pack_h2(q6 * e90, q7 * e100);
    if ((h0 | h1 | h2 | h3) != 0u)
        red_add_h8(g_fp_hi + 4 * i_rind, h0, h1, h2, h3);
}

// ---------------------------------------------------------------------------
// K: main triple loop — persistent grid-stride, 2 triples/iteration.
// ---------------------------------------------------------------------------
#define TRI_BLOCKS 888   // 148 SMs x 6 CTAs
__global__ void __launch_bounds__(256) tri_kernel(
    const int4* __restrict__ ind3v,   // [N_TRI/2]
    float* __restrict__ fp)
{
    int stride = TRI_BLOCKS * 256;
    for (int v = blockIdx.x * blockDim.x + threadIdx.x; v < N_TRI / 2; v += stride) {
        int4 q = __ldg(&ind3v[v]);

        float4 A1 = __ldg(&g_pair[q.x]);
        float4 B1 = __ldg(&g_pair[q.y]);
        float4 A2 = __ldg(&g_pair[q.z]);
        float4 B2 = __ldg(&g_pair[q.w]);

        do_triple(q.x, q.y, A1, B1, fp);
        do_triple(q.z, q.w, A2, B2, fp);
    }
}

// ---------------------------------------------------------------------------
// K: jacob_ind + convert fp16 channel accumulators to fp32 output
// ---------------------------------------------------------------------------
__global__ void __launch_bounds__(256) jac_kernel(float2* __restrict__ out_j,
                                                 float* __restrict__ fp)
{
    int p = blockIdx.x * blockDim.x + threadIdx.x;
    if (p < N_PAIR) {
        int ikmax = g_pair_max[p];
        int rv    = g_flag[p] ? g_rind[p] : -1;
        int v     = ikmax > rv ? ikmax : rv;
        out_j[p] = make_float2((float)p, (float)v);
    }
    if (p < N_ATOM) {
        uint4 raw = *reinterpret_cast<const uint4*>(g_fp_hi + 4 * p);
        float2 f0 = __half22float2(*reinterpret_cast<__half2*>(&raw.x));
        float2 f1 = __half22float2(*reinterpret_cast<__half2*>(&raw.y));
        float2 f2 = __half22float2(*reinterpret_cast<__half2*>(&raw.z));
        float2 f3 = __half22float2(*reinterpret_cast<__half2*>(&raw.w));
        float4* dst = reinterpret_cast<float4*>(fp + p * N_SF + 8);
        dst[0] = make_float4(f0.x, f0.y, f1.x, f1.y);
        dst[1] = make_float4(f2.x, f2.y, f3.x, f3.y);
    }
}

// ---------------------------------------------------------------------------
// Launch. Inputs: ind_2, ind_3, dist(unused), diff, elems(unused), fc(unused)
// ---------------------------------------------------------------------------
extern "C" void kernel_launch(void* const* d_in, const int* in_sizes, int n_in,
                              void* d_out, int out_size)
{
    const int*  ind2  = (const int*)d_in[0];
    const int4* ind3v = (const int4*)d_in[1];
    const float* diff = (const float*)d_in[3];

    float*  fp    = (float*)d_out;
    float2* out_j = (float2*)((float*)d_out + N_ATOM * N_SF);

    pack_init_kernel<<<(N_PAIR + 255) / 256, 256>>>(ind2, diff, fp);
    tri_kernel<<<TRI_BLOCKS, 256>>>(ind3v, fp);
    jac_kernel<<<(N_PAIR + 255) / 256, 256>>>(out_j, fp);
}